// round 7
// baseline (speedup 1.0000x reference)
#include <cuda_runtime.h>

typedef unsigned long long ull;

__device__ __forceinline__ ull pk2(float v) {
    ull d; asm("mov.b64 %0, {%1, %1};" : "=l"(d) : "f"(v)); return d;
}
__device__ __forceinline__ ull fma2(ull a, ull b, ull c) {
    ull d; asm("fma.rn.f32x2 %0, %1, %2, %3;" : "=l"(d) : "l"(a), "l"(b), "l"(c)); return d;
}
__device__ __forceinline__ float lo2(ull v) { return __uint_as_float((unsigned)v); }
__device__ __forceinline__ float hi2(ull v) { return __uint_as_float((unsigned)(v >> 32)); }

// level = clamp(rint(v), 0, inf); caller pre-clamps top at 3; sat.u32 maps negatives to 0
__device__ __forceinline__ int qlev(float v) {
    unsigned r; asm("cvt.rni.sat.u32.f32 %0, %1;" : "=r"(r) : "f"(v));
    return (int)r;
}
__device__ __forceinline__ int pack4(int a, int b, int c, int d) {
    int ab, cd, r;
    asm("prmt.b32 %0, %1, %2, 0x0040;" : "=r"(ab) : "r"(a), "r"(b));
    asm("prmt.b32 %0, %1, %2, 0x0040;" : "=r"(cd) : "r"(c), "r"(d));
    asm("prmt.b32 %0, %1, %2, 0x5410;" : "=r"(r) : "r"(ab), "r"(cd));
    return r;
}

__global__ __launch_bounds__(256, 3)
void net_all(const float* __restrict__ x,
             const float* __restrict__ w1,
             const float* __restrict__ w2,
             const float* __restrict__ wf,
             float* __restrict__ out) {
    __shared__ ull   sw1p[18];
    __shared__ int   sw2s[36];
    __shared__ int   swfs[497];   // 490 weights + 7 zero pad for FC split
    __shared__ float redm[8][3];
    __shared__ float sS[3];

    const int tid  = threadIdx.x;
    const int lane = tid & 31;
    const int wid  = tid >> 5;

    // ===== in-block prep: scales (order-independent max -> deterministic) =====
    {
        float m1 = 0.f, m2 = 0.f, mf = 0.f;
        if (tid < 36)  m1 = fabsf(__ldg(w1 + tid));
        if (tid < 144) m2 = fabsf(__ldg(w2 + tid));
        for (int i = tid; i < 1960; i += 256) mf = fmaxf(mf, fabsf(__ldg(wf + i)));
#pragma unroll
        for (int o = 16; o; o >>= 1) {
            m1 = fmaxf(m1, __shfl_xor_sync(0xffffffffu, m1, o));
            m2 = fmaxf(m2, __shfl_xor_sync(0xffffffffu, m2, o));
            mf = fmaxf(mf, __shfl_xor_sync(0xffffffffu, mf, o));
        }
        if (lane == 0) { redm[wid][0] = m1; redm[wid][1] = m2; redm[wid][2] = mf; }
        __syncthreads();
        if (tid < 3) {
            float a = redm[0][tid];
            for (int w = 1; w < 8; w++) a = fmaxf(a, redm[w][tid]);
            sS[tid] = a;
        }
        __syncthreads();
    }
    const float s1f = sS[0];
    const float s2  = sS[1];
    const float osc = 2.f * sS[2];

    // ===== in-block prep: pack weights into smem =====
    if (tid < 18) {
        int k = tid % 9, p = tid / 9;            // pair p covers channels 2p, 2p+1
        float wa = __ldg(w1 + (2 * p) * 9 + k);
        float wb = __ldg(w1 + (2 * p + 1) * 9 + k);
        float qa = fminf(fmaxf(rintf(wa / s1f), -1.f), 1.f) * s1f * 0.5f;  // pre-halved, exact
        float qb = fminf(fmaxf(rintf(wb / s1f), -1.f), 1.f) * s1f * 0.5f;
        ull lo = __float_as_uint(qa);
        ull hi = __float_as_uint(qb);
        sw1p[tid] = lo | (hi << 32);
    }
    if (tid >= 64 && tid < 100) {
        int t = tid - 64;
        int oc = t / 9, tap = t % 9;
        int word = 0;
        for (int ic = 0; ic < 4; ic++) {
            float w = __ldg(w2 + (oc * 4 + ic) * 9 + tap);
            int si = (int)rintf(w / s2);
            si = min(1, max(-1, si));
            word |= (si & 0xFF) << (8 * ic);
        }
        sw2s[t] = word;
    }
    for (int g = tid; g < 490; g += 256) {
        int o = g / 49, p = g % 49;
        int word = 0;
        for (int c = 0; c < 4; c++) {
            float w = __ldg(wf + o * 196 + c * 49 + p);
            int si = (int)rintf(w / sS[2]);
            si = min(1, max(-1, si));
            word |= (si & 0xFF) << (8 * c);
        }
        swfs[g] = word;
    }
    if (tid < 7) swfs[490 + tid] = 0;
    __syncthreads();

    // ===== main: one image per warp, lane-shifted column mapping =====
    const int  img = blockIdx.x * 8 + wid;
    const bool isA = lane < 16;
    const int  lx  = lane & 15;
    // pooled col lx-1 lives at lane 2*(lx-1)+1 = 2*lx-1; out-of-range (lx=0 pad, lx=15 pad)
    // must read a guaranteed-zero lane -> lane 31 (all its conv inputs are zero).
    int srcp = 2 * lx - 1;
    if (srcp < 0 || srcp > 27) srcp = 31;

    ull w01[9], w23[9];
#pragma unroll
    for (int k = 0; k < 9; k++) { w01[k] = sw1p[k]; w23[k] = sw1p[9 + k]; }

    // lane l holds column l-1; lane 0 = left zero pad; lanes 29..31 zero
    const bool   colOK = (lane >= 1) && (lane <= 28);
    const float* xcol  = x + (size_t)img * 784 + (lane - 1);
    float buf[4];
#pragma unroll
    for (int i = 0; i < 4; i++) buf[i] = colOK ? __ldg(xcol + i * 28) : 0.f;

    // ---- conv1 (FFMA2 streamed) + pool1 (quant-first, vmax4 horizontal) ----
    ull a01[3], a23[3];
    ull p01 = 0, p23 = 0;
    int arr[10];    // A: arr[0]=0, arr[t+1]=pooled row t (t<=8); B: arr[t-7]=row t (t>=7), rest 0
#pragma unroll
    for (int i = 0; i < 10; i++) arr[i] = 0;

#define C1_POOL(yc)                                                            \
    {                                                                          \
        const int s_ = (yc) % 3;                                               \
        if (((yc) & 1) == 0) { p01 = a01[s_]; p23 = a23[s_]; }                 \
        else {                                                                 \
            float v0 = fmaxf(lo2(p01), lo2(a01[s_]));                          \
            float v1 = fmaxf(hi2(p01), hi2(a01[s_]));                          \
            float v2 = fmaxf(lo2(p23), lo2(a23[s_]));                          \
            float v3 = fmaxf(hi2(p23), hi2(a23[s_]));                          \
            int l0 = qlev(fminf(v0, 3.f));                                     \
            int l1 = qlev(fminf(v1, 3.f));                                     \
            int l2 = qlev(fminf(v2, 3.f));                                     \
            int l3 = qlev(fminf(v3, 3.f));                                     \
            int word = pack4(l0, l1, l2, l3);                                  \
            word = __vmaxu4(word, __shfl_down_sync(0xffffffffu, word, 1));     \
            int rv = __shfl_sync(0xffffffffu, word, srcp);                     \
            const int t_ = (yc) >> 1;                                          \
            if (t_ <= 8 && isA)  arr[t_ + 1] = rv;                             \
            if (t_ >= 7 && !isA) arr[t_ - 7] = rv;                             \
        }                                                                      \
    }

#pragma unroll
    for (int r = 0; r < 28; r++) {
        float mv = buf[r & 3];
        if (r + 4 < 28) buf[r & 3] = colOK ? __ldg(xcol + (r + 4) * 28) : 0.f;
        float lf = __shfl_up_sync(0xffffffffu, mv, 1);     // lane0 keeps own = 0 pad
        float rt = __shfl_down_sync(0xffffffffu, mv, 1);   // lane28 reads lane29 = 0
        ull pl = pk2(lf), pm = pk2(mv), pr = pk2(rt);
#pragma unroll
        for (int ky = 0; ky < 3; ky++) {
            const int y = r + 1 - ky;
            if (y < 0 || y > 27) continue;
            const int s = y % 3;
            const bool fresh = (ky == 0) || (y == 0 && r == 0);
            ull c01 = fresh ? 0ull : a01[s];
            ull c23 = fresh ? 0ull : a23[s];
            c01 = fma2(w01[3 * ky + 0], pl, c01);
            c01 = fma2(w01[3 * ky + 1], pm, c01);
            c01 = fma2(w01[3 * ky + 2], pr, c01);
            c23 = fma2(w23[3 * ky + 0], pl, c23);
            c23 = fma2(w23[3 * ky + 1], pm, c23);
            c23 = fma2(w23[3 * ky + 2], pr, c23);
            a01[s] = c01; a23[s] = c23;
        }
        if (r >= 1) C1_POOL(r - 1);
        if (r == 27) C1_POOL(27);
    }

    // ---- conv2 (dp4a streamed, half-warp row split) + pool2 ----
    int w2r[36];
#pragma unroll
    for (int k = 0; k < 36; k++) w2r[k] = sw2s[k];

    int b0[3], b1[3], b2[3], b3[3];
    int q0 = 0, q1 = 0, q2 = 0, q3r = 0;
    int flat[4] = {0, 0, 0, 0};   // A: qy0..3; B: qy4..6 (flat[3] pad)

#pragma unroll
    for (int k = 0; k <= 9; k++) {
        int lv = arr[k];
        int lL = __shfl_up_sync(0xffffffffu, lv, 1);     // lane0 keeps own = 0; lane16 reads lane15 = 0 pad
        int lR = __shfl_down_sync(0xffffffffu, lv, 1);   // lane15/31 hold 0 pads
#pragma unroll
        for (int jj = 0; jj < 3; jj++) {
            const int j = k - jj;
            if (j < 0 || j > 7) continue;
            const int s = j % 3;
            const bool fresh = (jj == 0);
            int c0 = fresh ? 0 : b0[s];
            int c1 = fresh ? 0 : b1[s];
            int c2 = fresh ? 0 : b2[s];
            int c3 = fresh ? 0 : b3[s];
            c0 = __dp4a(lL, w2r[0 * 9 + jj * 3 + 0], c0);
            c0 = __dp4a(lv, w2r[0 * 9 + jj * 3 + 1], c0);
            c0 = __dp4a(lR, w2r[0 * 9 + jj * 3 + 2], c0);
            c1 = __dp4a(lL, w2r[1 * 9 + jj * 3 + 0], c1);
            c1 = __dp4a(lv, w2r[1 * 9 + jj * 3 + 1], c1);
            c1 = __dp4a(lR, w2r[1 * 9 + jj * 3 + 2], c1);
            c2 = __dp4a(lL, w2r[2 * 9 + jj * 3 + 0], c2);
            c2 = __dp4a(lv, w2r[2 * 9 + jj * 3 + 1], c2);
            c2 = __dp4a(lR, w2r[2 * 9 + jj * 3 + 2], c2);
            c3 = __dp4a(lL, w2r[3 * 9 + jj * 3 + 0], c3);
            c3 = __dp4a(lv, w2r[3 * 9 + jj * 3 + 1], c3);
            c3 = __dp4a(lR, w2r[3 * 9 + jj * 3 + 2], c3);
            b0[s] = c0; b1[s] = c1; b2[s] = c2; b3[s] = c3;
        }
        {   // output row j = k-2 complete
            const int j = k - 2;
            if (j >= 0) {
                const int s = j % 3;
                if ((j & 1) == 0) { q0 = b0[s]; q1 = b1[s]; q2 = b2[s]; q3r = b3[s]; }
                else {
                    int m0 = max(q0, b0[s]);
                    int m1 = max(q1, b1[s]);
                    int m2 = max(q2, b2[s]);
                    int m3 = max(q3r, b3[s]);
                    int l0 = qlev(fminf(s2 * (float)m0, 3.f));
                    int l1 = qlev(fminf(s2 * (float)m1, 3.f));
                    int l2 = qlev(fminf(s2 * (float)m2, 3.f));
                    int l3 = qlev(fminf(s2 * (float)m3, 3.f));
                    int word = pack4(l0, l1, l2, l3);
                    word = __vmaxu4(word, __shfl_down_sync(0xffffffffu, word, 1));
                    flat[(j - 1) >> 1] = word;   // valid at odd lanes 2qx+1 per half
                }
            }
        }
    }

    // ---- FC, split across half-warps: A qy0..3 (28 items), B qy4..6 (21 + 7 zero-pad) ----
    const int o = min(lx, 9);
    const int laneBase = o * 49 + (isA ? 0 : 28);
    const int grp = lane & 16;
    int facc = 0;
#pragma unroll
    for (int i = 0; i < 28; i++) {
        int word = __shfl_sync(0xffffffffu, flat[i / 7], grp + 2 * (i % 7) + 1);
        int widx = laneBase + i;
        if (i >= 21) widx = isA ? widx : 490;
        facc = __dp4a(word, swfs[widx], facc);
    }
    int bpart = __shfl_sync(0xffffffffu, facc, 16 + lx);
    if (lane < 10)
        out[(size_t)img * 10 + lane] = osc * (float)(facc + bpart);
}

extern "C" void kernel_launch(void* const* d_in, const int* in_sizes, int n_in,
                              void* d_out, int out_size) {
    const float* x  = (const float*)d_in[0];
    const float* w1 = (const float*)d_in[1];
    const float* w2 = (const float*)d_in[2];
    const float* wf = (const float*)d_in[3];
    float* out = (float*)d_out;

    int B = in_sizes[0] / 784;          // 32768 images, 8 warps/block = 1 image/warp
    net_all<<<B / 8, 256>>>(x, w1, w2, wf, out);
}

// round 8
// speedup vs baseline: 1.1668x; 1.1668x over previous
#include <cuda_runtime.h>

typedef unsigned long long ull;

// Packed weights produced by prep_kernel each launch.
__device__ ull   g_w1p[18];     // fp32x2 pairs: (ch 2p, ch 2p+1), pre-halved s1/2*sign, tap k
__device__ int   g_w2p[36];     // word[oc*9+tap], bytes = int8 sign per ic
__device__ int   g_wfp[490];    // word[o*49 + p], bytes = sign per channel c=0..3 (j = c*49+p)
__device__ float g_sc[2];       // {s2, 2*sf}

__global__ void prep_kernel(const float* __restrict__ w1,
                            const float* __restrict__ w2,
                            const float* __restrict__ wf) {
    __shared__ float redm[8][3];
    __shared__ float sS[3];
    const int tid = threadIdx.x, lane = tid & 31, wid = tid >> 5;

    float m1 = 0.f, m2 = 0.f, mf = 0.f;
    if (tid < 36)  m1 = fabsf(__ldg(w1 + tid));
    if (tid < 144) m2 = fabsf(__ldg(w2 + tid));
    for (int i = tid; i < 1960; i += 256) mf = fmaxf(mf, fabsf(__ldg(wf + i)));
#pragma unroll
    for (int o = 16; o; o >>= 1) {
        m1 = fmaxf(m1, __shfl_xor_sync(0xffffffffu, m1, o));
        m2 = fmaxf(m2, __shfl_xor_sync(0xffffffffu, m2, o));
        mf = fmaxf(mf, __shfl_xor_sync(0xffffffffu, mf, o));
    }
    if (lane == 0) { redm[wid][0] = m1; redm[wid][1] = m2; redm[wid][2] = mf; }
    __syncthreads();
    if (tid < 3) {
        float a = redm[0][tid];
        for (int w = 1; w < 8; w++) a = fmaxf(a, redm[w][tid]);
        sS[tid] = a;
    }
    __syncthreads();
    const float s1f = sS[0], s2 = sS[1], sf = sS[2];

    if (tid < 18) {
        int k = tid % 9, p = tid / 9;            // pair p covers channels 2p, 2p+1
        float wa = __ldg(w1 + (2 * p) * 9 + k);
        float wb = __ldg(w1 + (2 * p + 1) * 9 + k);
        float qa = fminf(fmaxf(rintf(wa / s1f), -1.f), 1.f) * s1f * 0.5f;  // pre-halved, exact
        float qb = fminf(fmaxf(rintf(wb / s1f), -1.f), 1.f) * s1f * 0.5f;
        ull lo = __float_as_uint(qa);
        ull hi = __float_as_uint(qb);
        g_w1p[tid] = lo | (hi << 32);
    }
    if (tid >= 64 && tid < 100) {
        int t = tid - 64;
        int oc = t / 9, tap = t % 9;
        int word = 0;
        for (int ic = 0; ic < 4; ic++) {
            float w = __ldg(w2 + (oc * 4 + ic) * 9 + tap);
            int si = (int)rintf(w / s2);
            si = min(1, max(-1, si));
            word |= (si & 0xFF) << (8 * ic);
        }
        g_w2p[t] = word;
    }
    for (int g = tid; g < 490; g += 256) {
        int o = g / 49, p = g % 49;
        int word = 0;
        for (int c = 0; c < 4; c++) {
            float w = __ldg(wf + o * 196 + c * 49 + p);
            int si = (int)rintf(w / sf);
            si = min(1, max(-1, si));
            word |= (si & 0xFF) << (8 * c);
        }
        g_wfp[g] = word;
    }
    if (tid == 0) { g_sc[0] = s2; g_sc[1] = 2.f * sf; }
}

__device__ __forceinline__ ull pk2(float v) {
    ull d; asm("mov.b64 %0, {%1, %1};" : "=l"(d) : "f"(v)); return d;
}
__device__ __forceinline__ ull fma2(ull a, ull b, ull c) {
    ull d; asm("fma.rn.f32x2 %0, %1, %2, %3;" : "=l"(d) : "l"(a), "l"(b), "l"(c)); return d;
}
__device__ __forceinline__ float lo2(ull v) { return __uint_as_float((unsigned)v); }
__device__ __forceinline__ float hi2(ull v) { return __uint_as_float((unsigned)(v >> 32)); }

// level = clamp(rint(v), 0, inf); caller pre-clamps top at 3; sat.u32 maps negatives to 0
__device__ __forceinline__ int qlev(float v) {
    unsigned r; asm("cvt.rni.sat.u32.f32 %0, %1;" : "=r"(r) : "f"(v));
    return (int)r;
}
__device__ __forceinline__ int pack4(int a, int b, int c, int d) {
    int ab, cd, r;
    asm("prmt.b32 %0, %1, %2, 0x0040;" : "=r"(ab) : "r"(a), "r"(b));
    asm("prmt.b32 %0, %1, %2, 0x0040;" : "=r"(cd) : "r"(c), "r"(d));
    asm("prmt.b32 %0, %1, %2, 0x5410;" : "=r"(r) : "r"(ab), "r"(cd));
    return r;
}

__global__ __launch_bounds__(256, 3)
void net_warp(const float* __restrict__ x, float* __restrict__ out) {
    __shared__ ull   sw1p[18];
    __shared__ int   sw2s[36];
    __shared__ int   swfs[497];   // 490 weights + 7 zero pad for FC split
    __shared__ float sscs[2];

    const int tid  = threadIdx.x;
    const int lane = tid & 31;
    const int wid  = tid >> 5;

    // stage packed weights (L2-resident globals)
    if (tid < 18) sw1p[tid] = g_w1p[tid];
    if (tid < 36) sw2s[tid] = g_w2p[tid];
    for (int i = tid; i < 490; i += 256) swfs[i] = g_wfp[i];
    if (tid >= 64 && tid < 71) swfs[490 + (tid - 64)] = 0;
    if (tid < 2) sscs[tid] = g_sc[tid];
    __syncthreads();

    // ===== main: one image per warp, lane-shifted column mapping =====
    const int  img = blockIdx.x * 8 + wid;
    const bool isA = lane < 16;
    const int  lx  = lane & 15;
    // pooled col lx-1 lives at lane 2*lx-1; out-of-range (lx=0 pad, lx=15 pad) reads
    // guaranteed-zero lane 31 (all its conv inputs are zero-pad lanes).
    int srcp = 2 * lx - 1;
    if (srcp < 0 || srcp > 27) srcp = 31;

    ull w01[9], w23[9];
#pragma unroll
    for (int k = 0; k < 9; k++) { w01[k] = sw1p[k]; w23[k] = sw1p[9 + k]; }
    const float s2  = sscs[0];
    const float osc = sscs[1];

    // lane l holds column l-1; lane 0 = left zero pad; lanes 29..31 zero
    const bool   colOK = (lane >= 1) && (lane <= 28);
    const float* xcol  = x + (size_t)img * 784 + (lane - 1);
    float buf[4];
#pragma unroll
    for (int i = 0; i < 4; i++) buf[i] = colOK ? __ldg(xcol + i * 28) : 0.f;

    // ---- conv1 (FFMA2 streamed) + pool1 (quant-first, vmax4 horizontal) ----
    ull a01[3], a23[3];
    ull p01 = 0, p23 = 0;
    int arr[10];    // A: arr[0]=0, arr[t+1]=pooled row t (t<=8); B: arr[t-7]=row t (t>=7), rest 0
#pragma unroll
    for (int i = 0; i < 10; i++) arr[i] = 0;

#define C1_POOL(yc)                                                            \
    {                                                                          \
        const int s_ = (yc) % 3;                                               \
        if (((yc) & 1) == 0) { p01 = a01[s_]; p23 = a23[s_]; }                 \
        else {                                                                 \
            float v0 = fmaxf(lo2(p01), lo2(a01[s_]));                          \
            float v1 = fmaxf(hi2(p01), hi2(a01[s_]));                          \
            float v2 = fmaxf(lo2(p23), lo2(a23[s_]));                          \
            float v3 = fmaxf(hi2(p23), hi2(a23[s_]));                          \
            int l0 = qlev(fminf(v0, 3.f));                                     \
            int l1 = qlev(fminf(v1, 3.f));                                     \
            int l2 = qlev(fminf(v2, 3.f));                                     \
            int l3 = qlev(fminf(v3, 3.f));                                     \
            int word = pack4(l0, l1, l2, l3);                                  \
            word = __vmaxu4(word, __shfl_down_sync(0xffffffffu, word, 1));     \
            int rv = __shfl_sync(0xffffffffu, word, srcp);                     \
            const int t_ = (yc) >> 1;                                          \
            if (t_ <= 8 && isA)  arr[t_ + 1] = rv;                             \
            if (t_ >= 7 && !isA) arr[t_ - 7] = rv;                             \
        }                                                                      \
    }

#pragma unroll
    for (int r = 0; r < 28; r++) {
        float mv = buf[r & 3];
        if (r + 4 < 28) buf[r & 3] = colOK ? __ldg(xcol + (r + 4) * 28) : 0.f;
        float lf = __shfl_up_sync(0xffffffffu, mv, 1);     // lane0 keeps own = 0 pad
        float rt = __shfl_down_sync(0xffffffffu, mv, 1);   // lane28 reads lane29 = 0
        ull pl = pk2(lf), pm = pk2(mv), pr = pk2(rt);
#pragma unroll
        for (int ky = 0; ky < 3; ky++) {
            const int y = r + 1 - ky;
            if (y < 0 || y > 27) continue;
            const int s = y % 3;
            const bool fresh = (ky == 0) || (y == 0 && r == 0);
            ull c01 = fresh ? 0ull : a01[s];
            ull c23 = fresh ? 0ull : a23[s];
            c01 = fma2(w01[3 * ky + 0], pl, c01);
            c01 = fma2(w01[3 * ky + 1], pm, c01);
            c01 = fma2(w01[3 * ky + 2], pr, c01);
            c23 = fma2(w23[3 * ky + 0], pl, c23);
            c23 = fma2(w23[3 * ky + 1], pm, c23);
            c23 = fma2(w23[3 * ky + 2], pr, c23);
            a01[s] = c01; a23[s] = c23;
        }
        if (r >= 1) C1_POOL(r - 1);
        if (r == 27) C1_POOL(27);
    }

    // ---- conv2 (dp4a streamed, half-warp row split) + pool2 ----
    int w2r[36];
#pragma unroll
    for (int k = 0; k < 36; k++) w2r[k] = sw2s[k];

    int b0[3], b1[3], b2[3], b3[3];
    int q0 = 0, q1 = 0, q2 = 0, q3r = 0;
    int flat[4] = {0, 0, 0, 0};   // A: qy0..3; B: qy4..6 (flat[3] pad)

#pragma unroll
    for (int k = 0; k <= 9; k++) {
        int lv = arr[k];
        int lL = __shfl_up_sync(0xffffffffu, lv, 1);     // lane0 keeps own = 0; lane16 reads lane15 = 0 pad
        int lR = __shfl_down_sync(0xffffffffu, lv, 1);   // lane15/31 hold 0 pads
#pragma unroll
        for (int jj = 0; jj < 3; jj++) {
            const int j = k - jj;
            if (j < 0 || j > 7) continue;
            const int s = j % 3;
            const bool fresh = (jj == 0);
            int c0 = fresh ? 0 : b0[s];
            int c1 = fresh ? 0 : b1[s];
            int c2 = fresh ? 0 : b2[s];
            int c3 = fresh ? 0 : b3[s];
            c0 = __dp4a(lL, w2r[0 * 9 + jj * 3 + 0], c0);
            c0 = __dp4a(lv, w2r[0 * 9 + jj * 3 + 1], c0);
            c0 = __dp4a(lR, w2r[0 * 9 + jj * 3 + 2], c0);
            c1 = __dp4a(lL, w2r[1 * 9 + jj * 3 + 0], c1);
            c1 = __dp4a(lv, w2r[1 * 9 + jj * 3 + 1], c1);
            c1 = __dp4a(lR, w2r[1 * 9 + jj * 3 + 2], c1);
            c2 = __dp4a(lL, w2r[2 * 9 + jj * 3 + 0], c2);
            c2 = __dp4a(lv, w2r[2 * 9 + jj * 3 + 1], c2);
            c2 = __dp4a(lR, w2r[2 * 9 + jj * 3 + 2], c2);
            c3 = __dp4a(lL, w2r[3 * 9 + jj * 3 + 0], c3);
            c3 = __dp4a(lv, w2r[3 * 9 + jj * 3 + 1], c3);
            c3 = __dp4a(lR, w2r[3 * 9 + jj * 3 + 2], c3);
            b0[s] = c0; b1[s] = c1; b2[s] = c2; b3[s] = c3;
        }
        {   // output row j = k-2 complete
            const int j = k - 2;
            if (j >= 0) {
                const int s = j % 3;
                if ((j & 1) == 0) { q0 = b0[s]; q1 = b1[s]; q2 = b2[s]; q3r = b3[s]; }
                else {
                    int m0 = max(q0, b0[s]);
                    int m1 = max(q1, b1[s]);
                    int m2 = max(q2, b2[s]);
                    int m3 = max(q3r, b3[s]);
                    int l0 = qlev(fminf(s2 * (float)m0, 3.f));
                    int l1 = qlev(fminf(s2 * (float)m1, 3.f));
                    int l2 = qlev(fminf(s2 * (float)m2, 3.f));
                    int l3 = qlev(fminf(s2 * (float)m3, 3.f));
                    int word = pack4(l0, l1, l2, l3);
                    word = __vmaxu4(word, __shfl_down_sync(0xffffffffu, word, 1));
                    flat[(j - 1) >> 1] = word;   // valid at odd lanes 2qx+1 per half
                }
            }
        }
    }

    // ---- FC, split across half-warps: A qy0..3 (28 items), B qy4..6 (21 + 7 zero-pad) ----
    const int o = min(lx, 9);
    const int laneBase = o * 49 + (isA ? 0 : 28);
    const int grp = lane & 16;
    int facc = 0;
#pragma unroll
    for (int i = 0; i < 28; i++) {
        int word = __shfl_sync(0xffffffffu, flat[i / 7], grp + 2 * (i % 7) + 1);
        int widx = laneBase + i;
        if (i >= 21) widx = isA ? widx : 490;
        facc = __dp4a(word, swfs[widx], facc);
    }
    int bpart = __shfl_sync(0xffffffffu, facc, 16 + lx);
    if (lane < 10)
        out[(size_t)img * 10 + lane] = osc * (float)(facc + bpart);
}

extern "C" void kernel_launch(void* const* d_in, const int* in_sizes, int n_in,
                              void* d_out, int out_size) {
    const float* x  = (const float*)d_in[0];
    const float* w1 = (const float*)d_in[1];
    const float* w2 = (const float*)d_in[2];
    const float* wf = (const float*)d_in[3];
    float* out = (float*)d_out;

    prep_kernel<<<1, 256>>>(w1, w2, wf);

    int B = in_sizes[0] / 784;          // 32768 images, 8 warps/block = 1 image/warp
    net_warp<<<B / 8, 256>>>(x, out);
}

// round 10
// speedup vs baseline: 1.2392x; 1.0621x over previous
#include <cuda_runtime.h>

typedef unsigned long long ull;

// Packed weights produced by prep_kernel each launch.
__device__ ull   g_w1p[18];     // fp32x2 pairs: (ch 2p, ch 2p+1), pre-halved s1/2*sign, tap k
__device__ int   g_w2p[36];     // word[oc*9+tap], bytes = int8 sign per ic
__device__ int   g_wfp[490];    // word[o*49 + p], bytes = sign per channel c (j = c*49+p)
__device__ float g_sc[2];       // {s2, 2*sf}

__global__ void prep_kernel(const float* __restrict__ w1,
                            const float* __restrict__ w2,
                            const float* __restrict__ wf) {
    __shared__ float redm[8][3];
    __shared__ float sS[3];
    const int tid = threadIdx.x, lane = tid & 31, wid = tid >> 5;

    float m1 = 0.f, m2 = 0.f, mf = 0.f;
    if (tid < 36)  m1 = fabsf(__ldg(w1 + tid));
    if (tid < 144) m2 = fabsf(__ldg(w2 + tid));
    for (int i = tid; i < 1960; i += 256) mf = fmaxf(mf, fabsf(__ldg(wf + i)));
#pragma unroll
    for (int o = 16; o; o >>= 1) {
        m1 = fmaxf(m1, __shfl_xor_sync(0xffffffffu, m1, o));
        m2 = fmaxf(m2, __shfl_xor_sync(0xffffffffu, m2, o));
        mf = fmaxf(mf, __shfl_xor_sync(0xffffffffu, mf, o));
    }
    if (lane == 0) { redm[wid][0] = m1; redm[wid][1] = m2; redm[wid][2] = mf; }
    __syncthreads();
    if (tid < 3) {
        float a = redm[0][tid];
        for (int w = 1; w < 8; w++) a = fmaxf(a, redm[w][tid]);
        sS[tid] = a;
    }
    __syncthreads();
    const float s1f = sS[0], s2 = sS[1], sf = sS[2];

    if (tid < 18) {
        int k = tid % 9, p = tid / 9;            // pair p covers channels 2p, 2p+1
        float wa = __ldg(w1 + (2 * p) * 9 + k);
        float wb = __ldg(w1 + (2 * p + 1) * 9 + k);
        float qa = fminf(fmaxf(rintf(wa / s1f), -1.f), 1.f) * s1f * 0.5f;  // pre-halved, exact
        float qb = fminf(fmaxf(rintf(wb / s1f), -1.f), 1.f) * s1f * 0.5f;
        ull lo = __float_as_uint(qa);
        ull hi = __float_as_uint(qb);
        g_w1p[tid] = lo | (hi << 32);
    }
    if (tid >= 64 && tid < 100) {
        int t = tid - 64;
        int oc = t / 9, tap = t % 9;
        int word = 0;
        for (int ic = 0; ic < 4; ic++) {
            float w = __ldg(w2 + (oc * 4 + ic) * 9 + tap);
            int si = (int)rintf(w / s2);
            si = min(1, max(-1, si));
            word |= (si & 0xFF) << (8 * ic);
        }
        g_w2p[t] = word;
    }
    for (int g = tid; g < 490; g += 256) {
        int o = g / 49, p = g % 49;
        int word = 0;
        for (int c = 0; c < 4; c++) {
            float w = __ldg(wf + o * 196 + c * 49 + p);
            int si = (int)rintf(w / sf);
            si = min(1, max(-1, si));
            word |= (si & 0xFF) << (8 * c);
        }
        g_wfp[g] = word;
    }
    if (tid == 0) { g_sc[0] = s2; g_sc[1] = 2.f * sf; }
}

__device__ __forceinline__ ull pk2(float v) {
    ull d; asm("mov.b64 %0, {%1, %1};" : "=l"(d) : "f"(v)); return d;
}
__device__ __forceinline__ ull fma2(ull a, ull b, ull c) {
    ull d; asm("fma.rn.f32x2 %0, %1, %2, %3;" : "=l"(d) : "l"(a), "l"(b), "l"(c)); return d;
}
__device__ __forceinline__ float lo2(ull v) { return __uint_as_float((unsigned)v); }
__device__ __forceinline__ float hi2(ull v) { return __uint_as_float((unsigned)(v >> 32)); }

// level = clamp(rint(v), 0, inf); caller pre-clamps top at 3; sat.u32 maps negatives to 0
__device__ __forceinline__ int qlev(float v) {
    unsigned r; asm("cvt.rni.sat.u32.f32 %0, %1;" : "=r"(r) : "f"(v));
    return (int)r;
}
__device__ __forceinline__ int pack4(int a, int b, int c, int d) {
    int ab, cd, r;
    asm("prmt.b32 %0, %1, %2, 0x0040;" : "=r"(ab) : "r"(a), "r"(b));
    asm("prmt.b32 %0, %1, %2, 0x0040;" : "=r"(cd) : "r"(c), "r"(d));
    asm("prmt.b32 %0, %1, %2, 0x5410;" : "=r"(r) : "r"(ab), "r"(cd));
    return r;
}

__global__ __launch_bounds__(256, 4)
void net_warp(const float* __restrict__ x, float* __restrict__ out) {
    __shared__ ull   sw1p[18];
    __shared__ int   sw2s[36];
    __shared__ int   swfs[497];   // 490 weights + 7 zero pad for FC split
    __shared__ float sscs[2];

    const int tid  = threadIdx.x;
    const int lane = tid & 31;
    const int wid  = tid >> 5;

    // stage packed weights (L2-resident globals)
    if (tid < 18) sw1p[tid] = g_w1p[tid];
    if (tid < 36) sw2s[tid] = g_w2p[tid];
    for (int i = tid; i < 490; i += 256) swfs[i] = g_wfp[i];
    if (tid >= 64 && tid < 71) swfs[490 + (tid - 64)] = 0;
    if (tid < 2) sscs[tid] = g_sc[tid];
    __syncthreads();

    const int  img = blockIdx.x * 8 + wid;
    const bool isA = lane < 16;
    const int  lx  = lane & 15;

    ull w01[9], w23[9];
#pragma unroll
    for (int k = 0; k < 9; k++) { w01[k] = sw1p[k]; w23[k] = sw1p[9 + k]; }
    const float s2  = sscs[0];
    const float osc = sscs[1];

    // ---- streaming input: one column per lane (lanes 28..31 zero), 4-deep prefetch ----
    const bool   colOK = lane < 28;
    const float* xcol  = x + (size_t)img * 784 + lane;
    float buf[4];
#pragma unroll
    for (int i = 0; i < 4; i++) buf[i] = colOK ? __ldg(xcol + i * 28) : 0.f;

    // ---- conv1 (FFMA2, rows streamed) + pool1 + quant + split-redistribution ----
    ull a01[3], a23[3];
    ull p01 = 0, p23 = 0;
    // arr: A lanes hold pooled rows 0..8; B lanes hold rows 7..13 in arr[0..6]
    int arr[9];
#pragma unroll
    for (int i = 0; i < 9; i++) arr[i] = 0;

#define C1_POOL(yc)                                                            \
    {                                                                          \
        const int s_ = (yc) % 3;                                               \
        if (((yc) & 1) == 0) { p01 = a01[s_]; p23 = a23[s_]; }                 \
        else {                                                                 \
            float v0 = fmaxf(lo2(p01), lo2(a01[s_]));                          \
            float v1 = fmaxf(hi2(p01), hi2(a01[s_]));                          \
            float v2 = fmaxf(lo2(p23), lo2(a23[s_]));                          \
            float v3 = fmaxf(hi2(p23), hi2(a23[s_]));                          \
            v0 = fmaxf(v0, __shfl_down_sync(0xffffffffu, v0, 1));              \
            v1 = fmaxf(v1, __shfl_down_sync(0xffffffffu, v1, 1));              \
            v2 = fmaxf(v2, __shfl_down_sync(0xffffffffu, v2, 1));              \
            v3 = fmaxf(v3, __shfl_down_sync(0xffffffffu, v3, 1));              \
            int l0 = qlev(fminf(v0, 3.f));                                     \
            int l1 = qlev(fminf(v1, 3.f));                                     \
            int l2 = qlev(fminf(v2, 3.f));                                     \
            int l3 = qlev(fminf(v3, 3.f));                                     \
            int word = pack4(l0, l1, l2, l3);                                  \
            int rv = __shfl_sync(0xffffffffu, word, lx * 2);                   \
            const int t_ = (yc) >> 1;                                          \
            if (t_ <= 8) arr[t_]     = isA  ? rv : arr[t_];                    \
            if (t_ >= 7) arr[t_ - 7] = !isA ? rv : arr[t_ - 7];                \
        }                                                                      \
    }

#pragma unroll
    for (int r = 0; r < 28; r++) {
        float mv = buf[r & 3];
        if (r + 4 < 28) buf[r & 3] = colOK ? __ldg(xcol + (r + 4) * 28) : 0.f;
        float lf = __shfl_up_sync(0xffffffffu, mv, 1);
        if (lane == 0) lf = 0.f;
        float rt = __shfl_down_sync(0xffffffffu, mv, 1);   // lane27 reads lane28 = 0
        ull pl = pk2(lf), pm = pk2(mv), pr = pk2(rt);
#pragma unroll
        for (int ky = 0; ky < 3; ky++) {
            const int y = r + 1 - ky;
            if (y < 0 || y > 27) continue;
            const int s = y % 3;
            const bool fresh = (ky == 0) || (y == 0 && r == 0);
            ull c01 = fresh ? 0ull : a01[s];
            ull c23 = fresh ? 0ull : a23[s];
            c01 = fma2(w01[3 * ky + 0], pl, c01);
            c01 = fma2(w01[3 * ky + 1], pm, c01);
            c01 = fma2(w01[3 * ky + 2], pr, c01);
            c23 = fma2(w23[3 * ky + 0], pl, c23);
            c23 = fma2(w23[3 * ky + 1], pm, c23);
            c23 = fma2(w23[3 * ky + 2], pr, c23);
            a01[s] = c01; a23[s] = c23;
        }
        if (r >= 1) C1_POOL(r - 1);
        if (r == 27) C1_POOL(27);
    }

    // ---- conv2, row-split across half-warps (A: out rows 0..7, B: out rows 8..13) ----
    // A stream: [zero, g0..g8]   -> lv = k ? arr[k-1] : 0
    // B stream: [g7..g13, 0, 0, 0] -> lv = (k<=6) ? arr[k] : 0
    int w2r[36];
#pragma unroll
    for (int k = 0; k < 36; k++) w2r[k] = sw2s[k];

    int b0[3], b1[3], b2[3], b3[3];
    int q0 = 0, q1 = 0, q2 = 0, q3r = 0;
    int flat[4];   // A: qy 0..3 at flat[0..3]; B: qy 4..6 at flat[0..2]
    const bool xz0 = (lx == 0), xz13 = (lx == 13);

#pragma unroll
    for (int k = 0; k <= 9; k++) {
        int lv;
        if (k == 0)      lv = isA ? 0 : arr[0];
        else if (k <= 6) lv = isA ? arr[k - 1] : arr[k];
        else             lv = isA ? arr[k - 1] : 0;
        int lL = __shfl_up_sync(0xffffffffu, lv, 1);
        if (xz0)  lL = 0;
        int lR = __shfl_down_sync(0xffffffffu, lv, 1);
        if (xz13) lR = 0;
#pragma unroll
        for (int jj = 0; jj < 3; jj++) {
            const int j = k - jj;                 // local output row
            if (j < 0 || j > 7) continue;
            const int s = j % 3;
            const bool fresh = (jj == 0);
            int c0 = fresh ? 0 : b0[s];
            int c1 = fresh ? 0 : b1[s];
            int c2 = fresh ? 0 : b2[s];
            int c3 = fresh ? 0 : b3[s];
            c0 = __dp4a(lL, w2r[0 * 9 + jj * 3 + 0], c0);
            c0 = __dp4a(lv, w2r[0 * 9 + jj * 3 + 1], c0);
            c0 = __dp4a(lR, w2r[0 * 9 + jj * 3 + 2], c0);
            c1 = __dp4a(lL, w2r[1 * 9 + jj * 3 + 0], c1);
            c1 = __dp4a(lv, w2r[1 * 9 + jj * 3 + 1], c1);
            c1 = __dp4a(lR, w2r[1 * 9 + jj * 3 + 2], c1);
            c2 = __dp4a(lL, w2r[2 * 9 + jj * 3 + 0], c2);
            c2 = __dp4a(lv, w2r[2 * 9 + jj * 3 + 1], c2);
            c2 = __dp4a(lR, w2r[2 * 9 + jj * 3 + 2], c2);
            c3 = __dp4a(lL, w2r[3 * 9 + jj * 3 + 0], c3);
            c3 = __dp4a(lv, w2r[3 * 9 + jj * 3 + 1], c3);
            c3 = __dp4a(lR, w2r[3 * 9 + jj * 3 + 2], c3);
            b0[s] = c0; b1[s] = c1; b2[s] = c2; b3[s] = c3;
        }
        // output row j = k-2 is now complete
        {
            const int j = k - 2;
            if (j >= 0) {
                const int s = j % 3;
                if ((j & 1) == 0) { q0 = b0[s]; q1 = b1[s]; q2 = b2[s]; q3r = b3[s]; }
                else {
                    int m0 = max(q0, b0[s]);
                    int m1 = max(q1, b1[s]);
                    int m2 = max(q2, b2[s]);
                    int m3 = max(q3r, b3[s]);
                    m0 = max(m0, __shfl_down_sync(0xffffffffu, m0, 1));
                    m1 = max(m1, __shfl_down_sync(0xffffffffu, m1, 1));
                    m2 = max(m2, __shfl_down_sync(0xffffffffu, m2, 1));
                    m3 = max(m3, __shfl_down_sync(0xffffffffu, m3, 1));
                    int l0 = qlev(fminf(s2 * (float)m0, 3.f));
                    int l1 = qlev(fminf(s2 * (float)m1, 3.f));
                    int l2 = qlev(fminf(s2 * (float)m2, 3.f));
                    int l3 = qlev(fminf(s2 * (float)m3, 3.f));
                    flat[(j - 1) >> 1] = pack4(l0, l1, l2, l3);
                }
            }
        }
    }

    // ---- FC, split across half-warps: A qy0..3 (28 items), B qy4..6 (21 + 7 zero-pad) ----
    const int o = min(lx, 9);
    const int laneBase = o * 49 + (isA ? 0 : 28);
    const int grp = lane & 16;
    int facc = 0;
#pragma unroll
    for (int i = 0; i < 28; i++) {
        int word = __shfl_sync(0xffffffffu, flat[i / 7], grp + 2 * (i % 7));
        int widx = laneBase + i;
        if (i >= 21) widx = isA ? widx : 490;
        facc = __dp4a(word, swfs[widx], facc);
    }
    int bpart = __shfl_sync(0xffffffffu, facc, 16 + lx);
    if (lane < 10)
        out[(size_t)img * 10 + lane] = osc * (float)(facc + bpart);
}

extern "C" void kernel_launch(void* const* d_in, const int* in_sizes, int n_in,
                              void* d_out, int out_size) {
    const float* x  = (const float*)d_in[0];
    const float* w1 = (const float*)d_in[1];
    const float* w2 = (const float*)d_in[2];
    const float* wf = (const float*)d_in[3];
    float* out = (float*)d_out;

    prep_kernel<<<1, 256>>>(w1, w2, wf);

    int B = in_sizes[0] / 784;          // 32768 images, 8 warps/block = 1 image/warp
    net_warp<<<B / 8, 256>>>(x, out);
}

// round 11
// speedup vs baseline: 1.3711x; 1.1064x over previous
#include <cuda_runtime.h>

typedef unsigned long long ull;

// Packed weights produced by prep_kernel each launch.
__device__ ull   g_w1p[18];     // fp32x2 pairs: (ch 2p, ch 2p+1), pre-halved s1/2*sign, tap k
__device__ int   g_w2p[36];     // word[oc*9+tap], bytes = int8 sign per ic
__device__ int   g_wfp[490];    // word[o*49 + p], bytes = sign per channel c (j = c*49+p)
__device__ float g_sc[2];       // {s2, 2*sf}

__global__ void prep_kernel(const float* __restrict__ w1,
                            const float* __restrict__ w2,
                            const float* __restrict__ wf) {
    __shared__ float swf[1960];
    __shared__ float redm[8][3];
    __shared__ float sS[3];
    const int tid = threadIdx.x, lane = tid & 31, wid = tid >> 5;

    // one global pass over wf: vectorized load -> smem + running max
    const float4* wf4 = (const float4*)wf;   // 1960 floats = 490 float4
    float m1 = 0.f, m2 = 0.f, mf = 0.f;
    for (int i = tid; i < 490; i += 256) {
        float4 v = __ldg(wf4 + i);
        swf[4 * i + 0] = v.x; swf[4 * i + 1] = v.y;
        swf[4 * i + 2] = v.z; swf[4 * i + 3] = v.w;
        mf = fmaxf(mf, fmaxf(fmaxf(fabsf(v.x), fabsf(v.y)),
                             fmaxf(fabsf(v.z), fabsf(v.w))));
    }
    if (tid < 36)  m1 = fabsf(__ldg(w1 + tid));
    if (tid < 144) m2 = fabsf(__ldg(w2 + tid));
#pragma unroll
    for (int o = 16; o; o >>= 1) {
        m1 = fmaxf(m1, __shfl_xor_sync(0xffffffffu, m1, o));
        m2 = fmaxf(m2, __shfl_xor_sync(0xffffffffu, m2, o));
        mf = fmaxf(mf, __shfl_xor_sync(0xffffffffu, mf, o));
    }
    if (lane == 0) { redm[wid][0] = m1; redm[wid][1] = m2; redm[wid][2] = mf; }
    __syncthreads();
    if (tid < 3) {
        float a = redm[0][tid];
        for (int w = 1; w < 8; w++) a = fmaxf(a, redm[w][tid]);
        sS[tid] = a;
    }
    __syncthreads();
    const float s1f = sS[0], s2 = sS[1], sf = sS[2];

    if (tid < 18) {
        int k = tid % 9, p = tid / 9;            // pair p covers channels 2p, 2p+1
        float wa = __ldg(w1 + (2 * p) * 9 + k);
        float wb = __ldg(w1 + (2 * p + 1) * 9 + k);
        float qa = fminf(fmaxf(rintf(wa / s1f), -1.f), 1.f) * s1f * 0.5f;  // pre-halved, exact
        float qb = fminf(fmaxf(rintf(wb / s1f), -1.f), 1.f) * s1f * 0.5f;
        ull lo = __float_as_uint(qa);
        ull hi = __float_as_uint(qb);
        g_w1p[tid] = lo | (hi << 32);
    }
    if (tid >= 64 && tid < 100) {
        int t = tid - 64;
        int oc = t / 9, tap = t % 9;
        int word = 0;
        for (int ic = 0; ic < 4; ic++) {
            float w = __ldg(w2 + (oc * 4 + ic) * 9 + tap);
            int si = (int)rintf(w / s2);
            si = min(1, max(-1, si));
            word |= (si & 0xFF) << (8 * ic);
        }
        g_w2p[t] = word;
    }
    for (int g = tid; g < 490; g += 256) {
        int o = g / 49, p = g % 49;
        int word = 0;
        for (int c = 0; c < 4; c++) {
            float w = swf[o * 196 + c * 49 + p];
            int si = (int)rintf(w / sf);
            si = min(1, max(-1, si));
            word |= (si & 0xFF) << (8 * c);
        }
        g_wfp[g] = word;
    }
    if (tid == 0) { g_sc[0] = s2; g_sc[1] = 2.f * sf; }
}

__device__ __forceinline__ ull pk2(float v) {
    ull d; asm("mov.b64 %0, {%1, %1};" : "=l"(d) : "f"(v)); return d;
}
__device__ __forceinline__ ull fma2(ull a, ull b, ull c) {
    ull d; asm("fma.rn.f32x2 %0, %1, %2, %3;" : "=l"(d) : "l"(a), "l"(b), "l"(c)); return d;
}
__device__ __forceinline__ float lo2(ull v) { return __uint_as_float((unsigned)v); }
__device__ __forceinline__ float hi2(ull v) { return __uint_as_float((unsigned)(v >> 32)); }

// level = rint(v) saturated below at 0 (top clamp done packed via vminu4)
__device__ __forceinline__ int qlev(float v) {
    unsigned r; asm("cvt.rni.sat.u32.f32 %0, %1;" : "=r"(r) : "f"(v));
    return (int)r;
}
__device__ __forceinline__ int pack4(int a, int b, int c, int d) {
    int ab, cd, r;
    asm("prmt.b32 %0, %1, %2, 0x0040;" : "=r"(ab) : "r"(a), "r"(b));
    asm("prmt.b32 %0, %1, %2, 0x0040;" : "=r"(cd) : "r"(c), "r"(d));
    asm("prmt.b32 %0, %1, %2, 0x5410;" : "=r"(r) : "r"(ab), "r"(cd));
    return r;
}

__global__ __launch_bounds__(256, 4)
void net_warp(const float* __restrict__ x, float* __restrict__ out) {
    __shared__ ull   sw1p[18];
    __shared__ int   sw2s[36];
    __shared__ int   swfs[497];   // 490 weights + 7 zero pad for FC split
    __shared__ float sscs[2];

    const int tid  = threadIdx.x;
    const int lane = tid & 31;
    const int wid  = tid >> 5;

    const int  img = blockIdx.x * 8 + wid;
    const bool isA = lane < 16;
    const int  lx  = lane & 15;

    // ---- input prefetch first: overlap with weight-staging L2 reads ----
    const bool   colOK = lane < 28;
    const float* xcol  = x + (size_t)img * 784 + lane;
    float buf[4];
#pragma unroll
    for (int i = 0; i < 4; i++) buf[i] = colOK ? __ldg(xcol + i * 28) : 0.f;

    // stage packed weights (L2-resident globals)
    if (tid < 18) sw1p[tid] = g_w1p[tid];
    if (tid < 36) sw2s[tid] = g_w2p[tid];
    for (int i = tid; i < 490; i += 256) swfs[i] = g_wfp[i];
    if (tid >= 64 && tid < 71) swfs[490 + (tid - 64)] = 0;
    if (tid < 2) sscs[tid] = g_sc[tid];
    __syncthreads();

    ull w01[9], w23[9];
#pragma unroll
    for (int k = 0; k < 9; k++) { w01[k] = sw1p[k]; w23[k] = sw1p[9 + k]; }
    const float s2  = sscs[0];
    const float osc = sscs[1];

    // ---- conv1 (FFMA2, rows streamed) + pool1 + quant + split-redistribution ----
    ull a01[3], a23[3];
    ull p01 = 0, p23 = 0;
    // arr: A lanes hold pooled rows 0..8; B lanes hold rows 7..13 in arr[0..6]
    int arr[9];
#pragma unroll
    for (int i = 0; i < 9; i++) arr[i] = 0;

// quant-first pooling: rint (sat at 0) per channel, pack, then packed-byte
// horizontal max + top clamp. Exact: rint/max commute (monotone), pre-quant
// magnitudes provably < 255 so bytes cannot overflow.
#define C1_POOL(yc)                                                            \
    {                                                                          \
        const int s_ = (yc) % 3;                                               \
        if (((yc) & 1) == 0) { p01 = a01[s_]; p23 = a23[s_]; }                 \
        else {                                                                 \
            float v0 = fmaxf(lo2(p01), lo2(a01[s_]));                          \
            float v1 = fmaxf(hi2(p01), hi2(a01[s_]));                          \
            float v2 = fmaxf(lo2(p23), lo2(a23[s_]));                          \
            float v3 = fmaxf(hi2(p23), hi2(a23[s_]));                          \
            int l0 = qlev(v0);                                                 \
            int l1 = qlev(v1);                                                 \
            int l2 = qlev(v2);                                                 \
            int l3 = qlev(v3);                                                 \
            int word = pack4(l0, l1, l2, l3);                                  \
            word = __vmaxu4(word, __shfl_down_sync(0xffffffffu, word, 1));     \
            word = __vminu4(word, 0x03030303);                                 \
            int rv = __shfl_sync(0xffffffffu, word, lx * 2);                   \
            const int t_ = (yc) >> 1;                                          \
            if (t_ <= 8) arr[t_]     = isA  ? rv : arr[t_];                    \
            if (t_ >= 7) arr[t_ - 7] = !isA ? rv : arr[t_ - 7];                \
        }                                                                      \
    }

#pragma unroll
    for (int r = 0; r < 28; r++) {
        float mv = buf[r & 3];
        if (r + 4 < 28) buf[r & 3] = colOK ? __ldg(xcol + (r + 4) * 28) : 0.f;
        float lf = __shfl_up_sync(0xffffffffu, mv, 1);
        if (lane == 0) lf = 0.f;
        float rt = __shfl_down_sync(0xffffffffu, mv, 1);   // lane27 reads lane28 = 0
        ull pl = pk2(lf), pm = pk2(mv), pr = pk2(rt);
#pragma unroll
        for (int ky = 0; ky < 3; ky++) {
            const int y = r + 1 - ky;
            if (y < 0 || y > 27) continue;
            const int s = y % 3;
            const bool fresh = (ky == 0) || (y == 0 && r == 0);
            ull c01 = fresh ? 0ull : a01[s];
            ull c23 = fresh ? 0ull : a23[s];
            c01 = fma2(w01[3 * ky + 0], pl, c01);
            c01 = fma2(w01[3 * ky + 1], pm, c01);
            c01 = fma2(w01[3 * ky + 2], pr, c01);
            c23 = fma2(w23[3 * ky + 0], pl, c23);
            c23 = fma2(w23[3 * ky + 1], pm, c23);
            c23 = fma2(w23[3 * ky + 2], pr, c23);
            a01[s] = c01; a23[s] = c23;
        }
        if (r >= 1) C1_POOL(r - 1);
        if (r == 27) C1_POOL(27);
    }

    // ---- conv2, row-split across half-warps (A: out rows 0..7, B: out rows 8..13) ----
    // A stream: [zero, g0..g8]   -> lv = k ? arr[k-1] : 0
    // B stream: [g7..g13, 0, 0, 0] -> lv = (k<=6) ? arr[k] : 0
    int w2r[36];
#pragma unroll
    for (int k = 0; k < 36; k++) w2r[k] = sw2s[k];

    int b0[3], b1[3], b2[3], b3[3];
    int q0 = 0, q1 = 0, q2 = 0, q3r = 0;
    int flat[4];   // A: qy 0..3 at flat[0..3]; B: qy 4..6 at flat[0..2]
    const bool xz0 = (lx == 0), xz13 = (lx == 13);

#pragma unroll
    for (int k = 0; k <= 9; k++) {
        int lv;
        if (k == 0)      lv = isA ? 0 : arr[0];
        else if (k <= 6) lv = isA ? arr[k - 1] : arr[k];
        else             lv = isA ? arr[k - 1] : 0;
        int lL = __shfl_up_sync(0xffffffffu, lv, 1);
        if (xz0)  lL = 0;
        int lR = __shfl_down_sync(0xffffffffu, lv, 1);
        if (xz13) lR = 0;
#pragma unroll
        for (int jj = 0; jj < 3; jj++) {
            const int j = k - jj;                 // local output row
            if (j < 0 || j > 7) continue;
            const int s = j % 3;
            const bool fresh = (jj == 0);
            int c0 = fresh ? 0 : b0[s];
            int c1 = fresh ? 0 : b1[s];
            int c2 = fresh ? 0 : b2[s];
            int c3 = fresh ? 0 : b3[s];
            c0 = __dp4a(lL, w2r[0 * 9 + jj * 3 + 0], c0);
            c0 = __dp4a(lv, w2r[0 * 9 + jj * 3 + 1], c0);
            c0 = __dp4a(lR, w2r[0 * 9 + jj * 3 + 2], c0);
            c1 = __dp4a(lL, w2r[1 * 9 + jj * 3 + 0], c1);
            c1 = __dp4a(lv, w2r[1 * 9 + jj * 3 + 1], c1);
            c1 = __dp4a(lR, w2r[1 * 9 + jj * 3 + 2], c1);
            c2 = __dp4a(lL, w2r[2 * 9 + jj * 3 + 0], c2);
            c2 = __dp4a(lv, w2r[2 * 9 + jj * 3 + 1], c2);
            c2 = __dp4a(lR, w2r[2 * 9 + jj * 3 + 2], c2);
            c3 = __dp4a(lL, w2r[3 * 9 + jj * 3 + 0], c3);
            c3 = __dp4a(lv, w2r[3 * 9 + jj * 3 + 1], c3);
            c3 = __dp4a(lR, w2r[3 * 9 + jj * 3 + 2], c3);
            b0[s] = c0; b1[s] = c1; b2[s] = c2; b3[s] = c3;
        }
        // output row j = k-2 is now complete
        {
            const int j = k - 2;
            if (j >= 0) {
                const int s = j % 3;
                if ((j & 1) == 0) { q0 = b0[s]; q1 = b1[s]; q2 = b2[s]; q3r = b3[s]; }
                else {
                    int m0 = max(q0, b0[s]);
                    int m1 = max(q1, b1[s]);
                    int m2 = max(q2, b2[s]);
                    int m3 = max(q3r, b3[s]);
                    int l0 = qlev(s2 * (float)m0);
                    int l1 = qlev(s2 * (float)m1);
                    int l2 = qlev(s2 * (float)m2);
                    int l3 = qlev(s2 * (float)m3);
                    int word = pack4(l0, l1, l2, l3);
                    word = __vmaxu4(word, __shfl_down_sync(0xffffffffu, word, 1));
                    word = __vminu4(word, 0x03030303);
                    flat[(j - 1) >> 1] = word;   // valid at even lanes 2qx per half
                }
            }
        }
    }

    // ---- FC, split across half-warps: A qy0..3 (28 items), B qy4..6 (21 + 7 zero-pad) ----
    const int o = min(lx, 9);
    const int laneBase = o * 49 + (isA ? 0 : 28);
    const int grp = lane & 16;
    int facc = 0;
#pragma unroll
    for (int i = 0; i < 21; i++) {
        int word = __shfl_sync(0xffffffffu, flat[i / 7], grp + 2 * (i % 7));
        facc = __dp4a(word, swfs[laneBase + i], facc);
    }
    const int base2 = isA ? laneBase : 469;    // B tail (i=21..27) hits zero pad 490..496
#pragma unroll
    for (int i = 21; i < 28; i++) {
        int word = __shfl_sync(0xffffffffu, flat[3], grp + 2 * (i - 21));
        facc = __dp4a(word, swfs[base2 + i], facc);
    }
    int bpart = __shfl_sync(0xffffffffu, facc, 16 + lx);
    if (lane < 10)
        out[(size_t)img * 10 + lane] = osc * (float)(facc + bpart);
}

extern "C" void kernel_launch(void* const* d_in, const int* in_sizes, int n_in,
                              void* d_out, int out_size) {
    const float* x  = (const float*)d_in[0];
    const float* w1 = (const float*)d_in[1];
    const float* w2 = (const float*)d_in[2];
    const float* wf = (const float*)d_in[3];
    float* out = (float*)d_out;

    prep_kernel<<<1, 256>>>(w1, w2, wf);

    int B = in_sizes[0] / 784;          // 32768 images, 8 warps/block = 1 image/warp
    net_warp<<<B / 8, 256>>>(x, out);
}

// round 14
// speedup vs baseline: 1.3761x; 1.0037x over previous
#include <cuda_runtime.h>

typedef unsigned long long ull;

// Packed weights produced by prep_kernel each launch.
__device__ ull   g_w1p[18];     // fp32x2 pairs: (ch 2p, ch 2p+1), pre-halved s1/2*sign, tap k
__device__ int   g_w2p[36];     // word[oc*9+tap], bytes = int8 sign per ic
__device__ int   g_wfp[490];    // word[o*49 + p], bytes = sign per channel c (j = c*49+p)
__device__ float g_sc[2];       // {s2, 2*sf}

__global__ void prep_kernel(const float* __restrict__ w1,
                            const float* __restrict__ w2,
                            const float* __restrict__ wf) {
    __shared__ float swf[1960];
    __shared__ float redm[8][3];
    __shared__ float sS[3];
    const int tid = threadIdx.x, lane = tid & 31, wid = tid >> 5;

    const float4* wf4 = (const float4*)wf;   // 1960 floats = 490 float4
    float m1 = 0.f, m2 = 0.f, mf = 0.f;
    for (int i = tid; i < 490; i += 256) {
        float4 v = __ldg(wf4 + i);
        swf[4 * i + 0] = v.x; swf[4 * i + 1] = v.y;
        swf[4 * i + 2] = v.z; swf[4 * i + 3] = v.w;
        mf = fmaxf(mf, fmaxf(fmaxf(fabsf(v.x), fabsf(v.y)),
                             fmaxf(fabsf(v.z), fabsf(v.w))));
    }
    if (tid < 36)  m1 = fabsf(__ldg(w1 + tid));
    if (tid < 144) m2 = fabsf(__ldg(w2 + tid));
#pragma unroll
    for (int o = 16; o; o >>= 1) {
        m1 = fmaxf(m1, __shfl_xor_sync(0xffffffffu, m1, o));
        m2 = fmaxf(m2, __shfl_xor_sync(0xffffffffu, m2, o));
        mf = fmaxf(mf, __shfl_xor_sync(0xffffffffu, mf, o));
    }
    if (lane == 0) { redm[wid][0] = m1; redm[wid][1] = m2; redm[wid][2] = mf; }
    __syncthreads();
    if (tid < 3) {
        float a = redm[0][tid];
        for (int w = 1; w < 8; w++) a = fmaxf(a, redm[w][tid]);
        sS[tid] = a;
    }
    __syncthreads();
    const float s1f = sS[0], s2 = sS[1], sf = sS[2];

    if (tid < 18) {
        int k = tid % 9, p = tid / 9;
        float wa = __ldg(w1 + (2 * p) * 9 + k);
        float wb = __ldg(w1 + (2 * p + 1) * 9 + k);
        float qa = fminf(fmaxf(rintf(wa / s1f), -1.f), 1.f) * s1f * 0.5f;  // pre-halved, exact
        float qb = fminf(fmaxf(rintf(wb / s1f), -1.f), 1.f) * s1f * 0.5f;
        ull lo = __float_as_uint(qa);
        ull hi = __float_as_uint(qb);
        g_w1p[tid] = lo | (hi << 32);
    }
    if (tid >= 64 && tid < 100) {
        int t = tid - 64;
        int oc = t / 9, tap = t % 9;
        int word = 0;
        for (int ic = 0; ic < 4; ic++) {
            float w = __ldg(w2 + (oc * 4 + ic) * 9 + tap);
            int si = (int)rintf(w / s2);
            si = min(1, max(-1, si));
            word |= (si & 0xFF) << (8 * ic);
        }
        g_w2p[t] = word;
    }
    for (int g = tid; g < 490; g += 256) {
        int o = g / 49, p = g % 49;
        int word = 0;
        for (int c = 0; c < 4; c++) {
            float w = swf[o * 196 + c * 49 + p];
            int si = (int)rintf(w / sf);
            si = min(1, max(-1, si));
            word |= (si & 0xFF) << (8 * c);
        }
        g_wfp[g] = word;
    }
    if (tid == 0) { g_sc[0] = s2; g_sc[1] = 2.f * sf; }
}

__device__ __forceinline__ ull pk2(float v) {
    ull d; asm("mov.b64 %0, {%1, %1};" : "=l"(d) : "f"(v)); return d;
}
__device__ __forceinline__ ull fma2(ull a, ull b, ull c) {
    ull d; asm("fma.rn.f32x2 %0, %1, %2, %3;" : "=l"(d) : "l"(a), "l"(b), "l"(c)); return d;
}
__device__ __forceinline__ float lo2(ull v) { return __uint_as_float((unsigned)v); }
__device__ __forceinline__ float hi2(ull v) { return __uint_as_float((unsigned)(v >> 32)); }

// level = rint(v) saturated below at 0 (top clamp done packed via vminu4)
__device__ __forceinline__ int qlev(float v) {
    unsigned r; asm("cvt.rni.sat.u32.f32 %0, %1;" : "=r"(r) : "f"(v));
    return (int)r;
}
__device__ __forceinline__ int pack4(int a, int b, int c, int d) {
    int ab, cd, r;
    asm("prmt.b32 %0, %1, %2, 0x0040;" : "=r"(ab) : "r"(a), "r"(b));
    asm("prmt.b32 %0, %1, %2, 0x0040;" : "=r"(cd) : "r"(c), "r"(d));
    asm("prmt.b32 %0, %1, %2, 0x5410;" : "=r"(r) : "r"(ab), "r"(cd));
    return r;
}

__global__ __launch_bounds__(256, 4)
void net_warp(const float* __restrict__ x, float* __restrict__ out) {
    __shared__ ull   sw1p[18];
    __shared__ int   sw2s[36];
    __shared__ int   swfs[497];   // 490 weights + 7 zero pad for FC split
    __shared__ float sscs[2];

    const int tid  = threadIdx.x;
    const int lane = tid & 31;
    const int wid  = tid >> 5;

    const int  img = blockIdx.x * 8 + wid;
    const bool isA = lane < 16;
    const int  lx  = lane & 15;

    // ---- input prefetch first: overlap with weight-staging L2 reads ----
    const bool   colOK = lane < 28;
    const float* xcol  = x + (size_t)img * 784 + lane;
    float buf[4];
#pragma unroll
    for (int i = 0; i < 4; i++) buf[i] = colOK ? __ldg(xcol + i * 28) : 0.f;

    // stage packed weights (L2-resident globals)
    if (tid < 18) sw1p[tid] = g_w1p[tid];
    if (tid < 36) sw2s[tid] = g_w2p[tid];
    for (int i = tid; i < 490; i += 256) swfs[i] = g_wfp[i];
    if (tid >= 64 && tid < 71) swfs[490 + (tid - 64)] = 0;
    if (tid < 2) sscs[tid] = g_sc[tid];
    __syncthreads();

    ull w01[9], w23[9];
#pragma unroll
    for (int k = 0; k < 9; k++) { w01[k] = sw1p[k]; w23[k] = sw1p[9 + k]; }
    const float s2  = sscs[0];
    const float osc = sscs[1];

    // Redistribution source: lane lx receives pooled COLUMN lx-1 (lanes 0 and 15
    // receive the zero pad, sourced from provably-zero lane 31).
    // Pooled col c lives at lane 2c after the horizontal vmax.
    int srcp = 2 * lx - 2;
    if (srcp < 0 || srcp > 26) srcp = 31;

    // ---- conv1 (FFMA2, rows streamed) + pool1 + quant + split-redistribution ----
    // Per-iteration order: ky=2 (completes row r-1), ky=1, POOL pair (r-2, r-1)
    // on even r, ky=0 (fresh row r+1). The pool reads its slots before the
    // fresh write recycles them -> no accumulator copies needed.
    ull a01[3], a23[3];
    // arr = conv2 input row stream. A: arr[0]=0 pad, arr[1+t]=pooled row t (t<=8);
    //       B: arr[t-7]=pooled row t (t>=7), arr[7..9]=0 pad.
    int arr[10];
#pragma unroll
    for (int i = 0; i < 10; i++) arr[i] = 0;

#define C1_POOL2(y)                                                            \
    {                                                                          \
        const int se = (y) % 3, so = ((y) + 1) % 3;                            \
        float v0 = fmaxf(lo2(a01[se]), lo2(a01[so]));                          \
        float v1 = fmaxf(hi2(a01[se]), hi2(a01[so]));                          \
        float v2 = fmaxf(lo2(a23[se]), lo2(a23[so]));                          \
        float v3 = fmaxf(hi2(a23[se]), hi2(a23[so]));                          \
        int l0 = qlev(v0);                                                     \
        int l1 = qlev(v1);                                                     \
        int l2 = qlev(v2);                                                     \
        int l3 = qlev(v3);                                                     \
        int word = pack4(l0, l1, l2, l3);                                      \
        word = __vmaxu4(word, __shfl_down_sync(0xffffffffu, word, 1));         \
        word = __vminu4(word, 0x03030303);                                     \
        int rv = __shfl_sync(0xffffffffu, word, srcp);                         \
        const int t_ = (y) >> 1;                                               \
        if (t_ <= 8 && isA)  arr[t_ + 1] = rv;                                 \
        if (t_ >= 7 && !isA) arr[t_ - 7] = rv;                                 \
    }

#pragma unroll
    for (int r = 0; r < 28; r++) {
        float mv = buf[r & 3];
        if (r + 4 < 28) buf[r & 3] = colOK ? __ldg(xcol + (r + 4) * 28) : 0.f;
        float lf = __shfl_up_sync(0xffffffffu, mv, 1);
        if (lane == 0) lf = 0.f;
        float rt = __shfl_down_sync(0xffffffffu, mv, 1);   // lane27 reads lane28 = 0
        ull pl = pk2(lf), pm = pk2(mv), pr = pk2(rt);

        // ky=2: completes output row r-1 (slot (r-1)%3)
        if (r >= 1) {
            const int s = (r - 1) % 3;
            ull c01 = a01[s], c23 = a23[s];
            c01 = fma2(w01[6], pl, c01);
            c01 = fma2(w01[7], pm, c01);
            c01 = fma2(w01[8], pr, c01);
            c23 = fma2(w23[6], pl, c23);
            c23 = fma2(w23[7], pm, c23);
            c23 = fma2(w23[8], pr, c23);
            a01[s] = c01; a23[s] = c23;
        }
        // ky=1: output row r (fresh only at r==0: row 0 has no ky=0 contribution)
        {
            const int s = r % 3;
            ull c01 = (r == 0) ? 0ull : a01[s];
            ull c23 = (r == 0) ? 0ull : a23[s];
            c01 = fma2(w01[3], pl, c01);
            c01 = fma2(w01[4], pm, c01);
            c01 = fma2(w01[5], pr, c01);
            c23 = fma2(w23[3], pl, c23);
            c23 = fma2(w23[4], pm, c23);
            c23 = fma2(w23[5], pr, c23);
            a01[s] = c01; a23[s] = c23;
        }
        // pool pair (r-2, r-1): slots still intact (fresh write happens below)
        if (r >= 2 && (r & 1) == 0) C1_POOL2(r - 2);
        // ky=0: fresh output row r+1 (slot (r+1)%3 == (r-2)%3, recycled)
        if (r <= 26) {
            const int s = (r + 1) % 3;
            ull c01 = fma2(w01[0], pl, 0ull);
            c01 = fma2(w01[1], pm, c01);
            c01 = fma2(w01[2], pr, c01);
            ull c23 = fma2(w23[0], pl, 0ull);
            c23 = fma2(w23[1], pm, c23);
            c23 = fma2(w23[2], pr, c23);
            a01[s] = c01; a23[s] = c23;
        }
    }
    C1_POOL2(26);   // final pair (26, 27)

    // ---- conv2 (dp4a, padded stream, half-warp row split) + pool2 ----
    // lane l computes output column l-1 (lanes 0/15/16/31 = zero pads, discarded).
    // Same reorder trick: jj=2 completes j=k-2, jj=1, POOL pair (k-3,k-2) on odd k,
    // jj=0 fresh j=k (slot k%3 == (k-3)%3, recycled after the pool).
    int w2r[36];
#pragma unroll
    for (int k = 0; k < 36; k++) w2r[k] = sw2s[k];

    int b0[3], b1[3], b2[3], b3[3];
    int flat[4];   // A: qy 0..3; B: qy 4..6 at flat[0..2] (flat[3] garbage, zero-weighted)

#define C2_ACC(jj, s, fresh)                                                   \
    {                                                                          \
        int c0 = (fresh) ? 0 : b0[s];                                          \
        int c1 = (fresh) ? 0 : b1[s];                                          \
        int c2 = (fresh) ? 0 : b2[s];                                          \
        int c3 = (fresh) ? 0 : b3[s];                                          \
        c0 = __dp4a(lL, w2r[0 * 9 + (jj) * 3 + 0], c0);                        \
        c0 = __dp4a(lv, w2r[0 * 9 + (jj) * 3 + 1], c0);                        \
        c0 = __dp4a(lR, w2r[0 * 9 + (jj) * 3 + 2], c0);                        \
        c1 = __dp4a(lL, w2r[1 * 9 + (jj) * 3 + 0], c1);                        \
        c1 = __dp4a(lv, w2r[1 * 9 + (jj) * 3 + 1], c1);                        \
        c1 = __dp4a(lR, w2r[1 * 9 + (jj) * 3 + 2], c1);                        \
        c2 = __dp4a(lL, w2r[2 * 9 + (jj) * 3 + 0], c2);                        \
        c2 = __dp4a(lv, w2r[2 * 9 + (jj) * 3 + 1], c2);                        \
        c2 = __dp4a(lR, w2r[2 * 9 + (jj) * 3 + 2], c2);                        \
        c3 = __dp4a(lL, w2r[3 * 9 + (jj) * 3 + 0], c3);                        \
        c3 = __dp4a(lv, w2r[3 * 9 + (jj) * 3 + 1], c3);                        \
        c3 = __dp4a(lR, w2r[3 * 9 + (jj) * 3 + 2], c3);                        \
        b0[s] = c0; b1[s] = c1; b2[s] = c2; b3[s] = c3;                        \
    }

#define C2_POOL2(j)                                                            \
    {                                                                          \
        const int se = (j) % 3, so = ((j) + 1) % 3;                            \
        int m0 = max(b0[se], b0[so]);                                          \
        int m1 = max(b1[se], b1[so]);                                          \
        int m2 = max(b2[se], b2[so]);                                          \
        int m3 = max(b3[se], b3[so]);                                          \
        int l0 = qlev(s2 * (float)m0);                                         \
        int l1 = qlev(s2 * (float)m1);                                         \
        int l2 = qlev(s2 * (float)m2);                                         \
        int l3 = qlev(s2 * (float)m3);                                         \
        int word = pack4(l0, l1, l2, l3);                                      \
        word = __vmaxu4(word, __shfl_down_sync(0xffffffffu, word, 1));         \
        word = __vminu4(word, 0x03030303);                                     \
        flat[(j) >> 1] = word;   /* valid at odd lanes 2qx+1 per half */       \
    }

#pragma unroll
    for (int k = 0; k <= 9; k++) {
        int lv = arr[k];
        int lL = __shfl_up_sync(0xffffffffu, lv, 1);     // lane0 own=0; lane16 reads lane15=0
        int lR = __shfl_down_sync(0xffffffffu, lv, 1);   // lane14 reads lane15=0; lane30 reads lane31=0
        if (k >= 2) C2_ACC(2, (k - 2) % 3, false)        // completes j = k-2
        if (k >= 1 && k <= 8) C2_ACC(1, (k - 1) % 3, false)
        if (k >= 3 && (k & 1)) C2_POOL2(k - 3)           // pairs (0,1),(2,3),(4,5),(6,7)
        if (k <= 7) C2_ACC(0, k % 3, true)               // fresh j = k
    }

    // ---- FC, split across half-warps: A qy0..3 (28 items), B qy4..6 (21 + 7 zero-pad) ----
    const int o = min(lx, 9);
    const int laneBase = o * 49 + (isA ? 0 : 28);
    const int grp = lane & 16;
    int facc = 0;
#pragma unroll
    for (int i = 0; i < 21; i++) {
        int word = __shfl_sync(0xffffffffu, flat[i / 7], grp + 2 * (i % 7) + 1);
        facc = __dp4a(word, swfs[laneBase + i], facc);
    }
    const int base2 = isA ? laneBase : 469;    // B tail (i=21..27) hits zero pad 490..496
#pragma unroll
    for (int i = 21; i < 28; i++) {
        int word = __shfl_sync(0xffffffffu, flat[3], grp + 2 * (i - 21) + 1);
        facc = __dp4a(word, swfs[base2 + i], facc);
    }
    int bpart = __shfl_sync(0xffffffffu, facc, 16 + lx);
    if (lane < 10)
        out[(size_t)img * 10 + lane] = osc * (float)(facc + bpart);
}

extern "C" void kernel_launch(void* const* d_in, const int* in_sizes, int n_in,
                              void* d_out, int out_size) {
    const float* x  = (const float*)d_in[0];
    const float* w1 = (const float*)d_in[1];
    const float* w2 = (const float*)d_in[2];
    const float* wf = (const float*)d_in[3];
    float* out = (float*)d_out;

    prep_kernel<<<1, 256>>>(w1, w2, wf);

    int B = in_sizes[0] / 784;          // 32768 images, 8 warps/block = 1 image/warp
    net_warp<<<B / 8, 256>>>(x, out);
}